// round 16
// baseline (speedup 1.0000x reference)
#include <cuda_runtime.h>
#include <cuda_fp16.h>
#include <cstdint>

#define Dn 12
#define Nn 32768
#define Ln 3
#define Kn 4
#define H 128
#define CH 896            // packed output channels per node: 512 f + 128 i + 128 u + 128 o
#define KA 640            // A width: 128 (x) + 512 (h_flat)
#define KE 384            // embedding GEMM K = L*H

// -------- device scratch (no cudaMalloc allowed) --------
__device__ float  g_t[Dn * Nn * H];              // f32 t (skip/output precision)
__device__ __half g_th[Dn * Nn * H];             // fp16 mirror of t (GEMM A input)
__device__ __half g_acth[(size_t)Nn * CH];       // activated gates; f-region holds sigma*c products
__device__ __half g_h[2][(Nn + 1) * H];          // ping-pong h (fp16, GEMM A input)
__device__ float  g_c[2][(Nn + 1) * H];          // ping-pong c (f32)
__device__ __half g_wp[CH * KA];                 // packed weights, mma-fragment-PERMUTED layout
__device__ float  g_bs[CH];                      // packed per-layer bias

__device__ __forceinline__ void mma_f16(float* d, const uint32_t* a, const uint32_t* b) {
    asm volatile(
        "mma.sync.aligned.m16n8k16.row.col.f32.f16.f16.f32 "
        "{%0,%1,%2,%3}, {%4,%5,%6,%7}, {%8,%9}, {%0,%1,%2,%3};"
        : "+f"(d[0]), "+f"(d[1]), "+f"(d[2]), "+f"(d[3])
        : "r"(a[0]), "r"(a[1]), "r"(a[2]), "r"(a[3]), "r"(b[0]), "r"(b[1]));
}

__device__ __forceinline__ uint32_t f2h2(float a, float b) {
    __half2 h = __floats2half2_rn(a, b);
    return *(uint32_t*)&h;
}
__device__ __forceinline__ float sigf(float x) { return 1.f / (1.f + __expf(-x)); }

__device__ __forceinline__ void cp_async16(uint32_t dst, const void* src) {
    asm volatile("cp.async.ca.shared.global [%0], [%1], 16;" :: "r"(dst), "l"(src));
}
#define CP_COMMIT() asm volatile("cp.async.commit_group;" ::: "memory")
#define CP_WAIT1()  asm volatile("cp.async.wait_group 1;" ::: "memory")

__device__ __forceinline__ void ldmx4(uint32_t* r, uint32_t a) {
    asm volatile("ldmatrix.sync.aligned.m8n8.x4.shared.b16 {%0,%1,%2,%3}, [%4];"
                 : "=r"(r[0]), "=r"(r[1]), "=r"(r[2]), "=r"(r[3]) : "r"(a));
}

// no-op: shifts ncu's -s 5 window so launch #6 is step_gemm(d=1)
__global__ void nop_kernel() {}

// ---------------- pack per-layer weights (fp16, fragment-permuted B) + zero h/c ----------------
__global__ void pack_kernel(const float* __restrict__ Uf_w, const float* __restrict__ Uf_b,
                            const float* __restrict__ Uiuo_w, const float* __restrict__ Uiuo_b,
                            const float* __restrict__ W_w, const float* __restrict__ W_b, int l) {
    int c = blockIdx.x;       // 0..895 pack; >=CH zero h/c
    int t = threadIdx.x;      // 0..639
    if (c >= CH) {
        size_t i = (size_t)(c - CH) * 640 + t;
        size_t n = (size_t)(Nn + 1) * H;
        if (i < n) {
            g_h[0][i] = __float2half(0.f); g_h[1][i] = __float2half(0.f);
            g_c[0][i] = 0.f; g_c[1][i] = 0.f;
        }
        return;
    }
    int wrow;
    const float* U;
    float b;
    if (c < 512) {            // f gates
        int j = c & 127;
        wrow = j;
        U = Uf_w + (size_t)(l * 512 + c) * 512;
        b = W_b[l * 512 + j] + Uf_b[l * 512 + c];
    } else {                  // i/u/o
        int q = c - 512;
        wrow = 128 + q;
        U = Uiuo_w + (size_t)(l * 384 + q) * 512;
        b = W_b[l * 512 + 128 + q] + Uiuo_b[l * 384 + q];
    }
    float v = (t < H) ? W_w[(size_t)(l * 512 + wrow) * H + t] : U[t - H];
    int ch = t >> 4;
    int w16 = t & 15;
    int hh = w16 >> 3;
    int p = (w16 & 7) >> 1;
    int lohi = w16 & 1;
    int u = 2 * p + hh;
    g_wp[(size_t)c * KA + ch * 16 + 2 * u + lohi] = __float2half(v);
    if (t == 0) g_bs[c] = b;
}

// ---------------- embedding GEMM via fp16 mma.sync (unchanged, proven) ----------------
__global__ void __launch_bounds__(256) embed_mma(const int* __restrict__ tokens,
                                                 const float* __restrict__ E,
                                                 const float* __restrict__ lin_w,
                                                 const float* __restrict__ lin_b) {
    __shared__ __half As[128][20];
    __shared__ __half Bs[128][20];
    int r0 = blockIdx.x * 128;
    int tid = threadIdx.x;
    int warp = tid >> 5;
    int lane = tid & 31;
    int g = lane >> 2;
    int q = lane & 3;
    int warp_m = (warp >> 2) * 64;
    int warp_n = (warp & 3) * 32;

    float acc[4][4][4];
#pragma unroll
    for (int i = 0; i < 4; i++)
#pragma unroll
        for (int j = 0; j < 4; j++)
#pragma unroll
            for (int v = 0; v < 4; v++) acc[i][j][v] = 0.f;

    int am = tid >> 1;
    int hh = tid & 1;
    int row = r0 + am;
    int tok0 = tokens[row * Ln + 0];
    int tok1 = tokens[row * Ln + 1];
    int tok2 = tokens[row * Ln + 2];
    const float* brow = lin_w + (size_t)am * KE;

    float4 va0, va1, vb0, vb1;
    {
        const float* src = E + (size_t)tok0 * H + hh * 8;
        va0 = ((const float4*)src)[0];
        va1 = ((const float4*)src)[1];
        const float4* bsrc = (const float4*)(brow + hh * 8);
        vb0 = bsrc[0];
        vb1 = bsrc[1];
    }

    for (int k0 = 0; k0 < KE; k0 += 16) {
        {
            uint32_t* pA = (uint32_t*)&As[am][0];
            pA[0 + hh] = f2h2(va0.x, va0.y);
            pA[2 + hh] = f2h2(va0.z, va0.w);
            pA[4 + hh] = f2h2(va1.x, va1.y);
            pA[6 + hh] = f2h2(va1.z, va1.w);
            uint32_t* pB = (uint32_t*)&Bs[am][0];
            pB[0 + hh] = f2h2(vb0.x, vb0.y);
            pB[2 + hh] = f2h2(vb0.z, vb0.w);
            pB[4 + hh] = f2h2(vb1.x, vb1.y);
            pB[6 + hh] = f2h2(vb1.z, vb1.w);
        }
        __syncthreads();

        if (k0 + 16 < KE) {
            int c = k0 + 16 + hh * 8;
            int slot = c >> 7;
            int j = c & 127;
            int tok = slot == 0 ? tok0 : (slot == 1 ? tok1 : tok2);
            const float* src = E + (size_t)tok * H + j;
            va0 = ((const float4*)src)[0];
            va1 = ((const float4*)src)[1];
            const float4* bsrc = (const float4*)(brow + k0 + 16 + hh * 8);
            vb0 = bsrc[0];
            vb1 = bsrc[1];
        }

        {
            uint32_t afr[4][4];
            uint32_t bfr[4][2];
#pragma unroll
            for (int i = 0; i < 4; i++) {
                int r = warp_m + i * 16 + g;
                uint2 lo = *(const uint2*)&As[r][4 * q];
                uint2 hi = *(const uint2*)&As[r + 8][4 * q];
                afr[i][0] = lo.x; afr[i][1] = hi.x; afr[i][2] = lo.y; afr[i][3] = hi.y;
            }
#pragma unroll
            for (int j = 0; j < 4; j++) {
                uint2 bv = *(const uint2*)&Bs[warp_n + j * 8 + g][4 * q];
                bfr[j][0] = bv.x; bfr[j][1] = bv.y;
            }
#pragma unroll
            for (int i = 0; i < 4; i++)
#pragma unroll
                for (int j = 0; j < 4; j++)
                    mma_f16(acc[i][j], afr[i], bfr[j]);
        }
        __syncthreads();
    }

#pragma unroll
    for (int i = 0; i < 4; i++) {
        int r = r0 + warp_m + i * 16 + g;
#pragma unroll
        for (int j = 0; j < 4; j++) {
            int col = warp_n + j * 8 + 2 * q;
            float b0 = lin_b[col], b1 = lin_b[col + 1];
            float lo0 = acc[i][j][0] + b0, lo1 = acc[i][j][1] + b1;
            float hi0 = acc[i][j][2] + b0, hi1 = acc[i][j][3] + b1;
            *(float2*)&g_t[(size_t)r * H + col] = make_float2(lo0, lo1);
            *(float2*)&g_t[(size_t)(r + 8) * H + col] = make_float2(hi0, hi1);
            *(uint32_t*)&g_th[(size_t)r * H + col] = f2h2(lo0, lo1);
            *(uint32_t*)&g_th[(size_t)(r + 8) * H + col] = f2h2(hi0, hi1);
        }
    }
}

// ---------------- per-step GEMM: k=32 chunks, cp.async 3-stage, ldmatrix A, B direct gmem ----------------
// f-gate CTAs (c0<512) store sigma(act)*c_prev products; others store activated gates.
#define APITCH 40                         // halves per row (80B: 16B-aligned, ldmatrix conflict-free)
#define ASTAGE (128 * APITCH)             // halves per stage
#define NCH 20                            // K chunks of 32
__global__ void __launch_bounds__(256, 2) step_gemm(const int* __restrict__ indices, int d, int prev) {
    __shared__ __half As[3][128][APITCH];
    int n0 = blockIdx.x * 128;
    int c0 = blockIdx.y * 128;
    int tid = threadIdx.x;
    int warp = tid >> 5;
    int lane = tid & 31;
    int g = lane >> 2;
    int q = lane & 3;
    int warp_m = (warp >> 2) * 64;
    int warp_n = (warp & 3) * 32;

    float acc[4][4][4];
#pragma unroll
    for (int i = 0; i < 4; i++)
#pragma unroll
        for (int j = 0; j < 4; j++)
#pragma unroll
            for (int v = 0; v < 4; v++) acc[i][j][v] = 0.f;

    int am = tid >> 1;
    int hh = tid & 1;
    int node = n0 + am;
    const __half* hprev = g_h[prev];
    const __half* xrow = g_th + ((size_t)d * Nn + node) * H;
    const int4 idxv = *(const int4*)(indices + ((size_t)d * Nn + node) * Kn);
    int safe0 = idxv.x < 0 ? 0 : idxv.x;
    int safe1 = idxv.y < 0 ? 0 : idxv.y;
    int safe2 = idxv.z < 0 ? 0 : idxv.z;
    int safe3 = idxv.w < 0 ? 0 : idxv.w;

    uint32_t smem_base = (uint32_t)__cvta_generic_to_shared(&As[0][0][0]);
    uint32_t dst_off = smem_base + (am * APITCH + hh * 16) * 2;
    uint32_t ldm_off = smem_base + ((warp_m + (lane & 15)) * APITCH + (lane >> 4) * 8) * 2;

    const uint32_t* wp32 = (const uint32_t*)g_wp;
    const uint32_t* bp[4];
#pragma unroll
    for (int j = 0; j < 4; j++)
        bp[j] = wp32 + (size_t)(c0 + warp_n + j * 8 + g) * (KA / 2) + 2 * q;

    auto asrc = [&](int ch) -> const __half* {
        int c = ch * 32 + hh * 16;
        if (c < H) return xrow + c;
        int kch = (c - H) >> 7;
        int j = (c - H) & 127;
        int safe = kch == 0 ? safe0 : (kch == 1 ? safe1 : (kch == 2 ? safe2 : safe3));
        return hprev + (size_t)safe * H + j;
    };

    // prologue: stages 0,1 <- chunks 0,1
    {
        const __half* s0 = asrc(0);
        cp_async16(dst_off, s0);
        cp_async16(dst_off + 16, s0 + 8);
        CP_COMMIT();
        const __half* s1 = asrc(1);
        cp_async16(dst_off + ASTAGE * 2, s1);
        cp_async16(dst_off + ASTAGE * 2 + 16, s1 + 8);
        CP_COMMIT();
    }
    uint2 bcur[4][2], bnext[4][2];
#pragma unroll
    for (int j = 0; j < 4; j++) {
        bcur[j][0] = *(const uint2*)(bp[j]);
        bcur[j][1] = *(const uint2*)(bp[j] + 8);
    }
    CP_WAIT1();
    __syncthreads();

    int s = 0;
#pragma unroll 1
    for (int ch = 0; ch < NCH; ch++) {
        if (ch + 2 < NCH) {
            int s2 = (s + 2 >= 3) ? s - 1 : s + 2;
            const __half* sp = asrc(ch + 2);
            cp_async16(dst_off + (uint32_t)s2 * ASTAGE * 2, sp);
            cp_async16(dst_off + (uint32_t)s2 * ASTAGE * 2 + 16, sp + 8);
        }
        CP_COMMIT();
        if (ch + 1 < NCH) {
#pragma unroll
            for (int j = 0; j < 4; j++) {
                bnext[j][0] = *(const uint2*)(bp[j] + (ch + 1) * 16);
                bnext[j][1] = *(const uint2*)(bp[j] + (ch + 1) * 16 + 8);
            }
        }

#pragma unroll
        for (int kg = 0; kg < 2; kg++) {
            uint32_t afr[4][4];
#pragma unroll
            for (int i = 0; i < 4; i++)
                ldmx4(afr[i], ldm_off + (uint32_t)s * ASTAGE * 2 + (i * 16 * APITCH + kg * 16) * 2);
#pragma unroll
            for (int i = 0; i < 4; i++)
#pragma unroll
                for (int j = 0; j < 4; j++)
                    mma_f16(acc[i][j], afr[i], (const uint32_t*)&bcur[j][kg]);
        }
#pragma unroll
        for (int j = 0; j < 4; j++) { bcur[j][0] = bnext[j][0]; bcur[j][1] = bnext[j][1]; }
        s = (s + 1 == 3) ? 0 : s + 1;
        CP_WAIT1();
        __syncthreads();
    }

    // store: f-CTAs fold in c_prev gather (sigma*c product); u block tanh; i/o sigmoid
    const bool isF = (c0 < 512);
    const bool isU = (c0 == 640);
    const int kgate = c0 >> 7;
    const float* cprev = g_c[prev];
#pragma unroll
    for (int i = 0; i < 4; i++) {
        int r = n0 + warp_m + i * 16 + g;
        int sc0 = 0, sc1 = 0;
        if (isF) {
            int i0 = indices[((size_t)d * Nn + r) * Kn + kgate];
            int i1 = indices[((size_t)d * Nn + r + 8) * Kn + kgate];
            sc0 = i0 < 0 ? 0 : i0;
            sc1 = i1 < 0 ? 0 : i1;
        }
#pragma unroll
        for (int j = 0; j < 4; j++) {
            int col = c0 + warp_n + j * 8 + 2 * q;
            float b0 = g_bs[col], b1 = g_bs[col + 1];
            float v00 = acc[i][j][0] + b0, v01 = acc[i][j][1] + b1;
            float v10 = acc[i][j][2] + b0, v11 = acc[i][j][3] + b1;
            float a00, a01, a10, a11;
            if (isU) {
                a00 = tanhf(v00); a01 = tanhf(v01); a10 = tanhf(v10); a11 = tanhf(v11);
            } else {
                a00 = sigf(v00); a01 = sigf(v01); a10 = sigf(v10); a11 = sigf(v11);
            }
            if (isF) {
                int jc = warp_n + j * 8 + 2 * q;   // channel within gate
                float2 cv0 = *(const float2*)&cprev[(size_t)sc0 * H + jc];
                float2 cv1 = *(const float2*)&cprev[(size_t)sc1 * H + jc];
                a00 *= cv0.x; a01 *= cv0.y; a10 *= cv1.x; a11 *= cv1.y;
            }
            *(uint32_t*)&g_acth[(size_t)r * CH + col] = f2h2(a00, a01);
            *(uint32_t*)&g_acth[(size_t)(r + 8) * CH + col] = f2h2(a10, a11);
        }
    }
}

// ---------------- gate epilogue (f-region already holds sigma*c products) ----------------
__global__ void __launch_bounds__(128) epilogue_kernel(const int* __restrict__ indices, int d, int prev) {
    int n = blockIdx.x;
    int j = threadIdx.x;
    const __half* act = g_acth + (size_t)n * CH;
    __half* hnext = g_h[prev ^ 1];
    float* cnext = g_c[prev ^ 1];

    float f = __half2float(act[0 * H + j]) + __half2float(act[1 * H + j])
            + __half2float(act[2 * H + j]) + __half2float(act[3 * H + j]);
    float ig = __half2float(act[512 + j]);
    float u  = __half2float(act[640 + j]);
    float o  = __half2float(act[768 + j]);
    float nc = ig * u + f;
    float nh = o * tanhf(nc);
    hnext[(size_t)(n + 1) * H + j] = __float2half(nh);
    cnext[(size_t)(n + 1) * H + j] = nc;
    size_t tpos = ((size_t)d * Nn + n) * H + j;
    float tn = nh + g_t[tpos];                   // skip connection
    g_t[tpos] = tn;
    g_th[tpos] = __float2half(tn);
}

// ---------------- final output ----------------
__global__ void final_out(float* __restrict__ out, int lastbuf) {
    size_t i = (size_t)blockIdx.x * blockDim.x + threadIdx.x;
    size_t nh = (size_t)Nn * H;
    if (i < nh) {
        float h = g_t[(size_t)(Dn - 1) * Nn * H + i];
        float c = g_c[lastbuf][H + i];
        out[i] = h;
        out[nh + i] = h;
        out[2 * nh + i] = c;
        out[3 * nh + i] = c;
    }
}

extern "C" void kernel_launch(void* const* d_in, const int* in_sizes, int n_in,
                              void* d_out, int out_size) {
    const int* tokens   = (const int*)d_in[0];
    const int* indices  = (const int*)d_in[1];
    const float* E      = (const float*)d_in[2];
    const float* lin_w  = (const float*)d_in[3];
    const float* lin_b  = (const float*)d_in[4];
    const float* Uf_w   = (const float*)d_in[5];
    const float* Uf_b   = (const float*)d_in[6];
    const float* Uiuo_w = (const float*)d_in[7];
    const float* Uiuo_b = (const float*)d_in[8];
    const float* W_w    = (const float*)d_in[9];
    const float* W_b    = (const float*)d_in[10];
    float* out = (float*)d_out;

    nop_kernel<<<1, 1>>>();   // shifts ncu -s 5 window onto step_gemm(d=1)

    embed_mma<<<(Dn * Nn) / 128, 256>>>(tokens, E, lin_w, lin_b);

    int zero_blocks = (int)(((size_t)(Nn + 1) * H + 639) / 640);
    for (int l = 0; l < 2; l++) {
        pack_kernel<<<CH + zero_blocks, KA>>>(Uf_w, Uf_b, Uiuo_w, Uiuo_b, W_w, W_b, l);
        for (int dd = 0; dd < Dn; dd++) {
            step_gemm<<<dim3(Nn / 128, CH / 128), 256>>>(indices, dd, dd & 1);
            epilogue_kernel<<<Nn, H>>>(indices, dd, dd & 1);
        }
    }
    final_out<<<((size_t)Nn * H + 255) / 256, 256>>>(out, 0);
}

// round 17
// speedup vs baseline: 1.2348x; 1.2348x over previous
#include <cuda_runtime.h>
#include <cuda_fp16.h>
#include <cstdint>

#define Dn 12
#define Nn 32768
#define Ln 3
#define Kn 4
#define H 128
#define CH 896            // packed output channels per node: 512 f + 128 i + 128 u + 128 o
#define KA 640            // A width: 128 (x) + 512 (h_flat)
#define KE 384            // embedding GEMM K = L*H

// -------- device scratch (no cudaMalloc allowed) --------
__device__ float  g_t[Dn * Nn * H];              // f32 t (skip/output precision)
__device__ __half g_th[Dn * Nn * H];             // fp16 mirror of t (GEMM A input)
__device__ __half g_acth[(size_t)Nn * CH];       // ACTIVATED gates for one step (fp16)
__device__ __half g_h[2][(Nn + 1) * H];          // ping-pong h (fp16, GEMM A input)
__device__ float  g_c[2][(Nn + 1) * H];          // ping-pong c (f32)
__device__ __half g_wp[CH * KA];                 // weights, FRAGMENT-INTERLEAVED layout (see pack)
__device__ float  g_bs[CH];                      // packed per-layer bias

__device__ __forceinline__ void mma_f16(float* d, const uint32_t* a, const uint32_t* b) {
    asm volatile(
        "mma.sync.aligned.m16n8k16.row.col.f32.f16.f16.f32 "
        "{%0,%1,%2,%3}, {%4,%5,%6,%7}, {%8,%9}, {%0,%1,%2,%3};"
        : "+f"(d[0]), "+f"(d[1]), "+f"(d[2]), "+f"(d[3])
        : "r"(a[0]), "r"(a[1]), "r"(a[2]), "r"(a[3]), "r"(b[0]), "r"(b[1]));
}

__device__ __forceinline__ uint32_t f2h2(float a, float b) {
    __half2 h = __floats2half2_rn(a, b);
    return *(uint32_t*)&h;
}
__device__ __forceinline__ float sigf(float x) { return 1.f / (1.f + __expf(-x)); }

__device__ __forceinline__ void cp_async16(uint32_t dst, const void* src) {
    asm volatile("cp.async.ca.shared.global [%0], [%1], 16;" :: "r"(dst), "l"(src));
}
#define CP_COMMIT() asm volatile("cp.async.commit_group;" ::: "memory")
#define CP_WAIT1()  asm volatile("cp.async.wait_group 1;" ::: "memory")

__device__ __forceinline__ void ldmx4(uint32_t* r, uint32_t a) {
    asm volatile("ldmatrix.sync.aligned.m8n8.x4.shared.b16 {%0,%1,%2,%3}, [%4];"
                 : "=r"(r[0]), "=r"(r[1]), "=r"(r[2]), "=r"(r[3]) : "r"(a));
}

// no-op: shifts ncu's -s 5 window so launch #6 is step_gemm(d=1)
__global__ void nop_kernel() {}

// ---------------- pack per-layer weights (fp16, FRAGMENT-INTERLEAVED) + zero h/c ----------------
// Layout: fragment block fb = (c>>3)*40 + (t>>4), 128 halves per block arranged as
// 32 lanes x 2 uint32: lane = (c&7)*4 + p, word = hh, half = lohi
// where w16 = t&15, hh = w16>>3, p = (w16&7)>>1, lohi = w16&1.
// A warp's B fragment (8-row group, k16 group) is ONE coalesced 256B uint2 load.
__global__ void pack_kernel(const float* __restrict__ Uf_w, const float* __restrict__ Uf_b,
                            const float* __restrict__ Uiuo_w, const float* __restrict__ Uiuo_b,
                            const float* __restrict__ W_w, const float* __restrict__ W_b, int l) {
    int c = blockIdx.x;       // 0..895 pack; >=CH zero h/c
    int t = threadIdx.x;      // 0..639
    if (c >= CH) {
        size_t i = (size_t)(c - CH) * 640 + t;
        size_t n = (size_t)(Nn + 1) * H;
        if (i < n) {
            g_h[0][i] = __float2half(0.f); g_h[1][i] = __float2half(0.f);
            g_c[0][i] = 0.f; g_c[1][i] = 0.f;
        }
        return;
    }
    int wrow;
    const float* U;
    float b;
    if (c < 512) {            // f gates
        int j = c & 127;
        wrow = j;
        U = Uf_w + (size_t)(l * 512 + c) * 512;
        b = W_b[l * 512 + j] + Uf_b[l * 512 + c];
    } else {                  // i/u/o
        int q = c - 512;
        wrow = 128 + q;
        U = Uiuo_w + (size_t)(l * 384 + q) * 512;
        b = W_b[l * 512 + 128 + q] + Uiuo_b[l * 384 + q];
    }
    float v = (t < H) ? W_w[(size_t)(l * 512 + wrow) * H + t] : U[t - H];
    int w16 = t & 15;
    int hh = w16 >> 3;
    int p = (w16 & 7) >> 1;
    int lohi = w16 & 1;
    size_t fb = (size_t)(c >> 3) * 40 + (t >> 4);
    int lane = (c & 7) * 4 + p;
    g_wp[fb * 128 + lane * 4 + hh * 2 + lohi] = __float2half(v);
    if (t == 0) g_bs[c] = b;
}

// ---------------- embedding GEMM via fp16 mma.sync (unchanged, proven) ----------------
__global__ void __launch_bounds__(256) embed_mma(const int* __restrict__ tokens,
                                                 const float* __restrict__ E,
                                                 const float* __restrict__ lin_w,
                                                 const float* __restrict__ lin_b) {
    __shared__ __half As[128][20];
    __shared__ __half Bs[128][20];
    int r0 = blockIdx.x * 128;
    int tid = threadIdx.x;
    int warp = tid >> 5;
    int lane = tid & 31;
    int g = lane >> 2;
    int q = lane & 3;
    int warp_m = (warp >> 2) * 64;
    int warp_n = (warp & 3) * 32;

    float acc[4][4][4];
#pragma unroll
    for (int i = 0; i < 4; i++)
#pragma unroll
        for (int j = 0; j < 4; j++)
#pragma unroll
            for (int v = 0; v < 4; v++) acc[i][j][v] = 0.f;

    int am = tid >> 1;
    int hh = tid & 1;
    int row = r0 + am;
    int tok0 = tokens[row * Ln + 0];
    int tok1 = tokens[row * Ln + 1];
    int tok2 = tokens[row * Ln + 2];
    const float* brow = lin_w + (size_t)am * KE;

    float4 va0, va1, vb0, vb1;
    {
        const float* src = E + (size_t)tok0 * H + hh * 8;
        va0 = ((const float4*)src)[0];
        va1 = ((const float4*)src)[1];
        const float4* bsrc = (const float4*)(brow + hh * 8);
        vb0 = bsrc[0];
        vb1 = bsrc[1];
    }

    for (int k0 = 0; k0 < KE; k0 += 16) {
        {
            uint32_t* pA = (uint32_t*)&As[am][0];
            pA[0 + hh] = f2h2(va0.x, va0.y);
            pA[2 + hh] = f2h2(va0.z, va0.w);
            pA[4 + hh] = f2h2(va1.x, va1.y);
            pA[6 + hh] = f2h2(va1.z, va1.w);
            uint32_t* pB = (uint32_t*)&Bs[am][0];
            pB[0 + hh] = f2h2(vb0.x, vb0.y);
            pB[2 + hh] = f2h2(vb0.z, vb0.w);
            pB[4 + hh] = f2h2(vb1.x, vb1.y);
            pB[6 + hh] = f2h2(vb1.z, vb1.w);
        }
        __syncthreads();

        if (k0 + 16 < KE) {
            int c = k0 + 16 + hh * 8;
            int slot = c >> 7;
            int j = c & 127;
            int tok = slot == 0 ? tok0 : (slot == 1 ? tok1 : tok2);
            const float* src = E + (size_t)tok * H + j;
            va0 = ((const float4*)src)[0];
            va1 = ((const float4*)src)[1];
            const float4* bsrc = (const float4*)(brow + k0 + 16 + hh * 8);
            vb0 = bsrc[0];
            vb1 = bsrc[1];
        }

        {
            uint32_t afr[4][4];
            uint32_t bfr[4][2];
#pragma unroll
            for (int i = 0; i < 4; i++) {
                int r = warp_m + i * 16 + g;
                uint2 lo = *(const uint2*)&As[r][4 * q];
                uint2 hi = *(const uint2*)&As[r + 8][4 * q];
                afr[i][0] = lo.x; afr[i][1] = hi.x; afr[i][2] = lo.y; afr[i][3] = hi.y;
            }
#pragma unroll
            for (int j = 0; j < 4; j++) {
                uint2 bv = *(const uint2*)&Bs[warp_n + j * 8 + g][4 * q];
                bfr[j][0] = bv.x; bfr[j][1] = bv.y;
            }
#pragma unroll
            for (int i = 0; i < 4; i++)
#pragma unroll
                for (int j = 0; j < 4; j++)
                    mma_f16(acc[i][j], afr[i], bfr[j]);
        }
        __syncthreads();
    }

#pragma unroll
    for (int i = 0; i < 4; i++) {
        int r = r0 + warp_m + i * 16 + g;
#pragma unroll
        for (int j = 0; j < 4; j++) {
            int col = warp_n + j * 8 + 2 * q;
            float b0 = lin_b[col], b1 = lin_b[col + 1];
            float lo0 = acc[i][j][0] + b0, lo1 = acc[i][j][1] + b1;
            float hi0 = acc[i][j][2] + b0, hi1 = acc[i][j][3] + b1;
            *(float2*)&g_t[(size_t)r * H + col] = make_float2(lo0, lo1);
            *(float2*)&g_t[(size_t)(r + 8) * H + col] = make_float2(hi0, hi1);
            *(uint32_t*)&g_th[(size_t)r * H + col] = f2h2(lo0, lo1);
            *(uint32_t*)&g_th[(size_t)(r + 8) * H + col] = f2h2(hi0, hi1);
        }
    }
}

// ---------------- per-step GEMM: k=32 chunks, cp.async 3-stage, ldmatrix A, coalesced-fragment B ----------------
#define APITCH 40                         // halves per row (80B: 16B-aligned, ldmatrix conflict-free)
#define ASTAGE (128 * APITCH)             // halves per stage
#define NCH 20                            // K chunks of 32
__global__ void __launch_bounds__(256, 2) step_gemm(const int* __restrict__ indices, int d, int prev) {
    __shared__ __half As[3][128][APITCH];
    int n0 = blockIdx.x * 128;
    int c0 = blockIdx.y * 128;
    int tid = threadIdx.x;
    int warp = tid >> 5;
    int lane = tid & 31;
    int g = lane >> 2;
    int q = lane & 3;
    int warp_m = (warp >> 2) * 64;
    int warp_n = (warp & 3) * 32;

    float acc[4][4][4];
#pragma unroll
    for (int i = 0; i < 4; i++)
#pragma unroll
        for (int j = 0; j < 4; j++)
#pragma unroll
            for (int v = 0; v < 4; v++) acc[i][j][v] = 0.f;

    int am = tid >> 1;
    int hh = tid & 1;
    int node = n0 + am;
    const __half* hprev = g_h[prev];
    const __half* xrow = g_th + ((size_t)d * Nn + node) * H;
    const int4 idxv = *(const int4*)(indices + ((size_t)d * Nn + node) * Kn);
    int safe0 = idxv.x < 0 ? 0 : idxv.x;
    int safe1 = idxv.y < 0 ? 0 : idxv.y;
    int safe2 = idxv.z < 0 ? 0 : idxv.z;
    int safe3 = idxv.w < 0 ? 0 : idxv.w;

    uint32_t smem_base = (uint32_t)__cvta_generic_to_shared(&As[0][0][0]);
    uint32_t dst_off = smem_base + (am * APITCH + hh * 16) * 2;
    uint32_t ldm_off = smem_base + ((warp_m + (lane & 15)) * APITCH + (lane >> 4) * 8) * 2;

    // B fragment pointers: fragment block fb = rowgroup*40 + kg16, 32 uint2 per block, lane-coalesced
    const uint2* wpu2 = (const uint2*)g_wp;
    const uint2* bfrag[4];
#pragma unroll
    for (int j = 0; j < 4; j++)
        bfrag[j] = wpu2 + (size_t)((c0 + warp_n + j * 8) >> 3) * 40 * 32 + lane;

    auto asrc = [&](int ch) -> const __half* {
        int c = ch * 32 + hh * 16;
        if (c < H) return xrow + c;
        int kch = (c - H) >> 7;
        int j = (c - H) & 127;
        int safe = kch == 0 ? safe0 : (kch == 1 ? safe1 : (kch == 2 ? safe2 : safe3));
        return hprev + (size_t)safe * H + j;
    };

    // prologue: stages 0,1 <- chunks 0,1
    {
        const __half* s0 = asrc(0);
        cp_async16(dst_off, s0);
        cp_async16(dst_off + 16, s0 + 8);
        CP_COMMIT();
        const __half* s1 = asrc(1);
        cp_async16(dst_off + ASTAGE * 2, s1);
        cp_async16(dst_off + ASTAGE * 2 + 16, s1 + 8);
        CP_COMMIT();
    }
    uint2 bcur[4][2], bnext[4][2];
#pragma unroll
    for (int j = 0; j < 4; j++) {
        bcur[j][0] = bfrag[j][0 * 32];
        bcur[j][1] = bfrag[j][1 * 32];
    }
    CP_WAIT1();
    __syncthreads();

    int s = 0;
    for (int ch = 0; ch < NCH; ch++) {
        if (ch + 2 < NCH) {
            int s2 = (s + 2 >= 3) ? s - 1 : s + 2;
            const __half* sp = asrc(ch + 2);
            cp_async16(dst_off + (uint32_t)s2 * ASTAGE * 2, sp);
            cp_async16(dst_off + (uint32_t)s2 * ASTAGE * 2 + 16, sp + 8);
        }
        CP_COMMIT();
        if (ch + 1 < NCH) {
#pragma unroll
            for (int j = 0; j < 4; j++) {
                bnext[j][0] = bfrag[j][(2 * (ch + 1) + 0) * 32];
                bnext[j][1] = bfrag[j][(2 * (ch + 1) + 1) * 32];
            }
        }

        // compute chunk ch from stage s: two k16 groups
#pragma unroll
        for (int kg = 0; kg < 2; kg++) {
            uint32_t afr[4][4];
#pragma unroll
            for (int i = 0; i < 4; i++)
                ldmx4(afr[i], ldm_off + (uint32_t)s * ASTAGE * 2 + (i * 16 * APITCH + kg * 16) * 2);
#pragma unroll
            for (int i = 0; i < 4; i++)
#pragma unroll
                for (int j = 0; j < 4; j++)
                    mma_f16(acc[i][j], afr[i], (const uint32_t*)&bcur[j][kg]);
        }
#pragma unroll
        for (int j = 0; j < 4; j++) { bcur[j][0] = bnext[j][0]; bcur[j][1] = bnext[j][1]; }
        s = (s + 1 == 3) ? 0 : s + 1;
        CP_WAIT1();
        __syncthreads();
    }

    // store ACTIVATED gates as fp16: sigmoid for f/i/o, tanh for u (cols 640..767)
#pragma unroll
    for (int i = 0; i < 4; i++) {
        int r = n0 + warp_m + i * 16 + g;
#pragma unroll
        for (int j = 0; j < 4; j++) {
            int col = c0 + warp_n + j * 8 + 2 * q;
            float b0 = g_bs[col], b1 = g_bs[col + 1];
            float v00 = acc[i][j][0] + b0, v01 = acc[i][j][1] + b1;
            float v10 = acc[i][j][2] + b0, v11 = acc[i][j][3] + b1;
            bool uu = (col >= 640 && col < 768);
            float a00 = uu ? tanhf(v00) : sigf(v00);
            float a01 = uu ? tanhf(v01) : sigf(v01);
            float a10 = uu ? tanhf(v10) : sigf(v10);
            float a11 = uu ? tanhf(v11) : sigf(v11);
            *(uint32_t*)&g_acth[(size_t)r * CH + col] = f2h2(a00, a01);
            *(uint32_t*)&g_acth[(size_t)(r + 8) * CH + col] = f2h2(a10, a11);
        }
    }
}

// ---------------- gate epilogue (reads activated fp16 gates) ----------------
__global__ void __launch_bounds__(128) epilogue_kernel(const int* __restrict__ indices, int d, int prev) {
    int n = blockIdx.x;
    int j = threadIdx.x;
    const __half* act = g_acth + (size_t)n * CH;
    const float* cprev = g_c[prev];
    __half* hnext = g_h[prev ^ 1];
    float* cnext = g_c[prev ^ 1];
    const int* idxp = indices + (size_t)(d * Nn + n) * Kn;

    float f = 0.f;
#pragma unroll
    for (int k = 0; k < Kn; k++) {
        int idx = idxp[k];
        int safe = idx < 0 ? 0 : idx;           // row 0 of c is zero -> mask implicit
        float cch = cprev[(size_t)safe * H + j];
        float fk = __half2float(act[k * H + j]);
        f += fk * cch;
    }
    float ig = __half2float(act[512 + j]);
    float u  = __half2float(act[640 + j]);
    float o  = __half2float(act[768 + j]);
    float nc = ig * u + f;
    float nh = o * tanhf(nc);
    hnext[(size_t)(n + 1) * H + j] = __float2half(nh);
    cnext[(size_t)(n + 1) * H + j] = nc;
    size_t tpos = ((size_t)d * Nn + n) * H + j;
    float tn = nh + g_t[tpos];                   // skip connection
    g_t[tpos] = tn;
    g_th[tpos] = __float2half(tn);
}

// ---------------- final output ----------------
__global__ void final_out(float* __restrict__ out, int lastbuf) {
    size_t i = (size_t)blockIdx.x * blockDim.x + threadIdx.x;
    size_t nh = (size_t)Nn * H;
    if (i < nh) {
        float h = g_t[(size_t)(Dn - 1) * Nn * H + i];
        float c = g_c[lastbuf][H + i];
        out[i] = h;
        out[nh + i] = h;
        out[2 * nh + i] = c;
        out[3 * nh + i] = c;
    }
}

extern "C" void kernel_launch(void* const* d_in, const int* in_sizes, int n_in,
                              void* d_out, int out_size) {
    const int* tokens   = (const int*)d_in[0];
    const int* indices  = (const int*)d_in[1];
    const float* E      = (const float*)d_in[2];
    const float* lin_w  = (const float*)d_in[3];
    const float* lin_b  = (const float*)d_in[4];
    const float* Uf_w   = (const float*)d_in[5];
    const float* Uf_b   = (const float*)d_in[6];
    const float* Uiuo_w = (const float*)d_in[7];
    const float* Uiuo_b = (const float*)d_in[8];
    const float* W_w    = (const float*)d_in[9];
    const float* W_b    = (const float*)d_in[10];
    float* out = (float*)d_out;

    nop_kernel<<<1, 1>>>();   // shifts ncu -s 5 window onto step_gemm(d=1)

    embed_mma<<<(Dn * Nn) / 128, 256>>>(tokens, E, lin_w, lin_b);

    int zero_blocks = (int)(((size_t)(Nn + 1) * H + 639) / 640);
    for (int l = 0; l < 2; l++) {
        pack_kernel<<<CH + zero_blocks, KA>>>(Uf_w, Uf_b, Uiuo_w, Uiuo_b, W_w, W_b, l);
        for (int dd = 0; dd < Dn; dd++) {
            step_gemm<<<dim3(Nn / 128, CH / 128), 256>>>(indices, dd, dd & 1);
            epilogue_kernel<<<Nn, H>>>(indices, dd, dd & 1);
        }
    }
    final_out<<<((size_t)Nn * H + 255) / 256, 256>>>(out, 0);
}